// round 12
// baseline (speedup 1.0000x reference)
#include <cuda_runtime.h>
#include <stdint.h>

#define N_STRUCT   1000
#define ATOMS      100
#define N_SAMP     100000
#define N_GRAD     500000
#define DFEAT      128
#define NSEG       (N_STRUCT * ATOMS)      // 100000
#define ROW_F4     96                      // 3*128/4
#define GRAD_OUT_OFFSET (N_STRUCT * DFEAT)

// prep: 148 worker blocks (1/SM), tile 680 segments each (148*680 >= 100000)
#define WORK_NB    148
#define TILE       680
#define PREP_THREADS (WORK_NB * 1024)          // 151552

#define VALUES_NB  ((N_STRUCT + 7) / 8)        // 125
#define PREP_BLOCKS (WORK_NB + VALUES_NB)      // 273 (all co-resident)

#define GATHER_BLOCKS (NSEG / 8)               // 12500 (8 warps/blk, 1 seg/warp)

// -------- scratch (device globals; zero-initialized at module load) --------
// Invariants at kernel_launch entry (restored by gather every call):
//   g_count == 0, g_bsum == 0, g_sync1 == 0, g_sync2 == 0
__device__ int g_count[NSEG];
__device__ int g_start[NSEG + 1];
__device__ int g_rows[N_GRAD];
__device__ int g_segpos[N_GRAD];   // (seg << 8) | within-segment rank
__device__ int g_bsum[WORK_NB];    // tile-sum + 1 (0 == not ready)
__device__ int g_sync1, g_sync2;   // grid-sync counters (worker blocks only)

// ---------------------------------------------------------------------------
// Kernel 1 (persistent prep):
//   bid <  WORK_NB : count(batched MLP) -> gridsync -> shfl-scan(+lookback)
//                    -> gridsync -> scatter(batched MLP)
//   bid >= WORK_NB : values segment-sums (no sync participation)
// ---------------------------------------------------------------------------
__global__ __launch_bounds__(1024) void prep_kernel(
        const int*   __restrict__ gstruct,
        const int*   __restrict__ gatom,
        const float* __restrict__ values,
        const int*   __restrict__ sid,
        float*       __restrict__ out) {
    if (blockIdx.x < WORK_NB) {
        int tid = threadIdx.x;
        int b   = blockIdx.x;
        int gth = b * 1024 + tid;

        // --- phase 1: degree count, batched (4 iters: loads, atomics, stores)
        {
            int r0 = gth;
            int r1 = r0 + PREP_THREADS;
            int r2 = r1 + PREP_THREADS;
            int r3 = r2 + PREP_THREADS;
            int s0 = -1, s1 = -1, s2 = -1, s3 = -1;
            if (r0 < N_GRAD) s0 = __ldcs(gstruct + r0) * ATOMS + __ldcs(gatom + r0);
            if (r1 < N_GRAD) s1 = __ldcs(gstruct + r1) * ATOMS + __ldcs(gatom + r1);
            if (r2 < N_GRAD) s2 = __ldcs(gstruct + r2) * ATOMS + __ldcs(gatom + r2);
            if (r3 < N_GRAD) s3 = __ldcs(gstruct + r3) * ATOMS + __ldcs(gatom + r3);
            int p0 = 0, p1 = 0, p2 = 0, p3 = 0;
            if (s0 >= 0) p0 = atomicAdd(&g_count[s0], 1);
            if (s1 >= 0) p1 = atomicAdd(&g_count[s1], 1);
            if (s2 >= 0) p2 = atomicAdd(&g_count[s2], 1);
            if (s3 >= 0) p3 = atomicAdd(&g_count[s3], 1);
            if (s0 >= 0) g_segpos[r0] = (s0 << 8) | p0;
            if (s1 >= 0) g_segpos[r1] = (s1 << 8) | p1;
            if (s2 >= 0) g_segpos[r2] = (s2 << 8) | p2;
            if (s3 >= 0) g_segpos[r3] = (s3 << 8) | p3;
        }
        __syncthreads();
        if (tid == 0) {
            __threadfence();
            atomicAdd(&g_sync1, 1);
            volatile int* p = &g_sync1;
            while (*p < WORK_NB) { }
        }
        __syncthreads();

        // --- phase 2: tile scan via warp-shfl (2 syncs) + decoupled lookback
        __shared__ int warp_sums[32];
        __shared__ int s_boff;
        int i = b * TILE + tid;
        int v = (tid < TILE && i < NSEG) ? g_count[i] : 0;

        int lane = tid & 31;
        int wid  = tid >> 5;
        // inclusive warp scan
        int x = v;
        #pragma unroll
        for (int off = 1; off < 32; off <<= 1) {
            int t = __shfl_up_sync(0xffffffffu, x, off);
            if (lane >= off) x += t;
        }
        if (lane == 31) warp_sums[wid] = x;
        __syncthreads();
        if (wid == 0) {
            int w = warp_sums[lane];
            #pragma unroll
            for (int off = 1; off < 32; off <<= 1) {
                int t = __shfl_up_sync(0xffffffffu, w, off);
                if (lane >= off) w += t;
            }
            warp_sums[lane] = w;                 // inclusive over warps
        }
        __syncthreads();
        int warp_base = (wid > 0) ? warp_sums[wid - 1] : 0;
        int incl = x + warp_base;                // inclusive scan of tile
        int tile_total = warp_sums[31];

        if (tid == 0) {
            volatile int* p = g_bsum;
            p[b] = tile_total + 1;               // publish (+1 = ready)
        }
        if (tid < 32) {                           // lookback j < b
            int acc = 0;
            volatile int* p = g_bsum;
            for (int j = tid; j < b; j += 32) {
                int w;
                while ((w = p[j]) == 0) { }
                acc += w - 1;
            }
            #pragma unroll
            for (int off = 16; off > 0; off >>= 1)
                acc += __shfl_down_sync(0xffffffffu, acc, off);
            if (tid == 0) s_boff = acc;
        }
        __syncthreads();
        if (tid < TILE && i < NSEG) g_start[i] = incl - v + s_boff;
        if (i == NSEG - 1) g_start[NSEG] = N_GRAD;

        __syncthreads();
        if (tid == 0) {
            __threadfence();
            atomicAdd(&g_sync2, 1);
            volatile int* p = &g_sync2;
            while (*p < WORK_NB) { }
        }
        __syncthreads();

        // --- phase 3: atomic-free scatter, batched ---
        {
            int r0 = gth;
            int r1 = r0 + PREP_THREADS;
            int r2 = r1 + PREP_THREADS;
            int r3 = r2 + PREP_THREADS;
            int sp0 = (r0 < N_GRAD) ? g_segpos[r0] : -1;
            int sp1 = (r1 < N_GRAD) ? g_segpos[r1] : -1;
            int sp2 = (r2 < N_GRAD) ? g_segpos[r2] : -1;
            int sp3 = (r3 < N_GRAD) ? g_segpos[r3] : -1;
            int o0 = 0, o1 = 0, o2 = 0, o3 = 0;
            if (sp0 >= 0) o0 = g_start[sp0 >> 8];
            if (sp1 >= 0) o1 = g_start[sp1 >> 8];
            if (sp2 >= 0) o2 = g_start[sp2 >> 8];
            if (sp3 >= 0) o3 = g_start[sp3 >> 8];
            if (sp0 >= 0) g_rows[o0 + (sp0 & 255)] = r0;
            if (sp1 >= 0) g_rows[o1 + (sp1 & 255)] = r1;
            if (sp2 >= 0) g_rows[o2 + (sp2 & 255)] = r2;
            if (sp3 >= 0) g_rows[o3 + (sp3 & 255)] = r3;
        }
    } else {
        // --- values segment-sum: 8 structures per block (sorted -> bsearch)
        int vb  = blockIdx.x - WORK_NB;
        int sub = threadIdx.x >> 7;            // 0..7
        int d   = threadIdx.x & 127;
        int s   = vb * 8 + sub;

        __shared__ int s_lo[8], s_hi[8];
        if (s < N_STRUCT) {
            if (d == 0) {
                int lo = 0, hi = N_SAMP;
                while (lo < hi) { int m = (lo + hi) >> 1; if (sid[m] < s) lo = m + 1; else hi = m; }
                s_lo[sub] = lo;
                lo = s_lo[sub]; hi = N_SAMP;
                while (lo < hi) { int m = (lo + hi) >> 1; if (sid[m] < s + 1) lo = m + 1; else hi = m; }
                s_hi[sub] = lo;
            }
        }
        __syncthreads();
        if (s >= N_STRUCT) return;

        int lo = s_lo[sub], hi = s_hi[sub];
        float a0 = 0.f, a1 = 0.f, a2 = 0.f, a3 = 0.f;
        int r = lo;
        for (; r + 3 < hi; r += 4) {
            a0 += __ldcs(values + (long long)(r    ) * DFEAT + d);
            a1 += __ldcs(values + (long long)(r + 1) * DFEAT + d);
            a2 += __ldcs(values + (long long)(r + 2) * DFEAT + d);
            a3 += __ldcs(values + (long long)(r + 3) * DFEAT + d);
        }
        for (; r < hi; ++r)
            a0 += __ldcs(values + (long long)r * DFEAT + d);
        __stcs(out + (long long)s * DFEAT + d, (a0 + a1) + (a2 + a3));
    }
}

// ---------------------------------------------------------------------------
// Kernel 2: gather-reduce — EXACT proven hot path (145us @ 6.1+TB/s).
// One warp per segment; row ids prefetched into lanes + shfl broadcast ->
// all 3*cnt loads address-ready. Restores all scratch invariants.
// ---------------------------------------------------------------------------
__global__ void gather_kernel(const float4* __restrict__ grad4,
                              float*        __restrict__ out_grad) {
    int zi = blockIdx.x * 256 + threadIdx.x;
    if (zi < NSEG) g_count[zi] = 0;
    if (zi < WORK_NB) g_bsum[zi] = 0;
    if (zi == 0) { g_sync1 = 0; g_sync2 = 0; }

    int warp_id = (blockIdx.x * 256 + threadIdx.x) >> 5;
    int lane    = threadIdx.x & 31;

    int lo  = g_start[warp_id];
    int hi  = g_start[warp_id + 1];
    int cnt = hi - lo;

    int rid = (lane < cnt) ? g_rows[lo + lane] : 0;

    float4 a0 = make_float4(0.f, 0.f, 0.f, 0.f);
    float4 a1 = a0, a2 = a0;

    int n32 = cnt < 32 ? cnt : 32;
    #pragma unroll 4
    for (int p = 0; p < n32; ++p) {
        long long row = __shfl_sync(0xffffffffu, rid, p);
        const float4* src = grad4 + row * ROW_F4;
        float4 v0 = __ldcs(src + lane);
        float4 v1 = __ldcs(src + lane + 32);
        float4 v2 = __ldcs(src + lane + 64);
        a0.x += v0.x; a0.y += v0.y; a0.z += v0.z; a0.w += v0.w;
        a1.x += v1.x; a1.y += v1.y; a1.z += v1.z; a1.w += v1.w;
        a2.x += v2.x; a2.y += v2.y; a2.z += v2.z; a2.w += v2.w;
    }
    for (int p = 32; p < cnt; ++p) {         // overflow fallback (never hit)
        long long row = g_rows[lo + p];
        const float4* src = grad4 + row * ROW_F4;
        float4 v0 = __ldcs(src + lane);
        float4 v1 = __ldcs(src + lane + 32);
        float4 v2 = __ldcs(src + lane + 64);
        a0.x += v0.x; a0.y += v0.y; a0.z += v0.z; a0.w += v0.w;
        a1.x += v1.x; a1.y += v1.y; a1.z += v1.z; a1.w += v1.w;
        a2.x += v2.x; a2.y += v2.y; a2.z += v2.z; a2.w += v2.w;
    }

    float4* dst = (float4*)(out_grad + (long long)warp_id * (3 * DFEAT));
    __stcs(dst + lane,      a0);
    __stcs(dst + lane + 32, a1);
    __stcs(dst + lane + 64, a2);
}

// ---------------------------------------------------------------------------
extern "C" void kernel_launch(void* const* d_in, const int* in_sizes, int n_in,
                              void* d_out, int out_size) {
    const float*  values  = (const float*)d_in[0];
    const int*    sid     = (const int*)  d_in[1];
    const float4* grad4   = (const float4*)d_in[2];
    const int*    gstruct = (const int*)  d_in[3];
    const int*    gatom   = (const int*)  d_in[4];

    float* out      = (float*)d_out;
    float* out_grad = out + GRAD_OUT_OFFSET;

    prep_kernel<<<PREP_BLOCKS, 1024>>>(gstruct, gatom, values, sid, out);
    gather_kernel<<<GATHER_BLOCKS, 256>>>(grad4, out_grad);
}

// round 13
// speedup vs baseline: 1.0021x; 1.0021x over previous
#include <cuda_runtime.h>
#include <stdint.h>

#define N_STRUCT   1000
#define ATOMS      100
#define N_SAMP     100000
#define N_GRAD     500000
#define DFEAT      128
#define NSEG       (N_STRUCT * ATOMS)      // 100000
#define ROW_F4     96                      // 3*128/4
#define GRAD_OUT_OFFSET (N_STRUCT * DFEAT)

// prep: 148 worker blocks (1/SM), tile 680 segments each (148*680 >= 100000)
#define WORK_NB    148
#define TILE       680
#define N_GRAD4    (N_GRAD / 4)                // 125000 int4 packets

#define VALUES_NB  ((N_STRUCT + 7) / 8)        // 125
#define PREP_BLOCKS (WORK_NB + VALUES_NB)      // 273 (all co-resident)

#define GATHER_BLOCKS (NSEG / 8)               // 12500 (8 warps/blk, 1 seg/warp)

// -------- scratch (device globals; zero-initialized at module load) --------
// Invariants at kernel_launch entry (restored by gather every call):
//   g_count == 0, g_bsum == 0, g_sync1 == 0, g_sync2 == 0
__device__ int g_count[NSEG];
__device__ int g_start[NSEG + 1];
__device__ int g_rows[N_GRAD];
__device__ int g_segpos[N_GRAD];   // (seg << 8) | within-segment rank
__device__ int g_bsum[WORK_NB];    // tile-sum + 1 (0 == not ready)
__device__ int g_sync1, g_sync2;   // grid-sync counters (worker blocks only)

// ---------------------------------------------------------------------------
// Kernel 1 (persistent prep):
//   bid <  WORK_NB : int4 count -> gridsync -> shfl-scan(+lookback)
//                    -> gridsync -> int4 scatter
//   bid >= WORK_NB : values segment-sums (no sync participation)
// ---------------------------------------------------------------------------
__global__ __launch_bounds__(1024) void prep_kernel(
        const int*   __restrict__ gstruct,
        const int*   __restrict__ gatom,
        const float* __restrict__ values,
        const int*   __restrict__ sid,
        float*       __restrict__ out) {
    if (blockIdx.x < WORK_NB) {
        int tid = threadIdx.x;
        int b   = blockIdx.x;
        int t   = b * 1024 + tid;              // packet index (4 rows each)

        // --- phase 1: degree count; one int4 packet (4 consecutive rows) ---
        if (t < N_GRAD4) {
            int4 gs = __ldcs((const int4*)gstruct + t);
            int4 ga = __ldcs((const int4*)gatom  + t);
            int s0 = gs.x * ATOMS + ga.x;
            int s1 = gs.y * ATOMS + ga.y;
            int s2 = gs.z * ATOMS + ga.z;
            int s3 = gs.w * ATOMS + ga.w;
            int p0 = atomicAdd(&g_count[s0], 1);
            int p1 = atomicAdd(&g_count[s1], 1);
            int p2 = atomicAdd(&g_count[s2], 1);
            int p3 = atomicAdd(&g_count[s3], 1);
            int4 sp;
            sp.x = (s0 << 8) | p0;
            sp.y = (s1 << 8) | p1;
            sp.z = (s2 << 8) | p2;
            sp.w = (s3 << 8) | p3;
            *((int4*)g_segpos + t) = sp;
        }
        __syncthreads();
        if (tid == 0) {
            __threadfence();
            atomicAdd(&g_sync1, 1);
            volatile int* p = &g_sync1;
            while (*p < WORK_NB) { }
        }
        __syncthreads();

        // --- phase 2: tile scan via warp-shfl + decoupled lookback ---
        __shared__ int warp_sums[32];
        __shared__ int s_boff;
        int i = b * TILE + tid;
        int v = (tid < TILE && i < NSEG) ? g_count[i] : 0;

        int lane = tid & 31;
        int wid  = tid >> 5;
        int x = v;
        #pragma unroll
        for (int off = 1; off < 32; off <<= 1) {
            int tmp = __shfl_up_sync(0xffffffffu, x, off);
            if (lane >= off) x += tmp;
        }
        if (lane == 31) warp_sums[wid] = x;
        __syncthreads();
        if (wid == 0) {
            int w = warp_sums[lane];
            #pragma unroll
            for (int off = 1; off < 32; off <<= 1) {
                int tmp = __shfl_up_sync(0xffffffffu, w, off);
                if (lane >= off) w += tmp;
            }
            warp_sums[lane] = w;                 // inclusive over warps
        }
        __syncthreads();
        int warp_base = (wid > 0) ? warp_sums[wid - 1] : 0;
        int incl = x + warp_base;
        int tile_total = warp_sums[31];

        if (tid == 0) {
            volatile int* p = g_bsum;
            p[b] = tile_total + 1;               // publish (+1 = ready)
        }
        if (tid < 32) {                           // lookback j < b
            int acc = 0;
            volatile int* p = g_bsum;
            for (int j = tid; j < b; j += 32) {
                int w;
                while ((w = p[j]) == 0) { }
                acc += w - 1;
            }
            #pragma unroll
            for (int off = 16; off > 0; off >>= 1)
                acc += __shfl_down_sync(0xffffffffu, acc, off);
            if (tid == 0) s_boff = acc;
        }
        __syncthreads();
        if (tid < TILE && i < NSEG) g_start[i] = incl - v + s_boff;
        if (i == NSEG - 1) g_start[NSEG] = N_GRAD;

        __syncthreads();
        if (tid == 0) {
            __threadfence();
            atomicAdd(&g_sync2, 1);
            volatile int* p = &g_sync2;
            while (*p < WORK_NB) { }
        }
        __syncthreads();

        // --- phase 3: atomic-free scatter; one int4 packet per thread ---
        if (t < N_GRAD4) {
            int4 sp = *((const int4*)g_segpos + t);
            int o0 = g_start[sp.x >> 8];
            int o1 = g_start[sp.y >> 8];
            int o2 = g_start[sp.z >> 8];
            int o3 = g_start[sp.w >> 8];
            int r  = t * 4;
            g_rows[o0 + (sp.x & 255)] = r;
            g_rows[o1 + (sp.y & 255)] = r + 1;
            g_rows[o2 + (sp.z & 255)] = r + 2;
            g_rows[o3 + (sp.w & 255)] = r + 3;
        }
    } else {
        // --- values segment-sum: 8 structures per block (sorted -> bsearch)
        int vb  = blockIdx.x - WORK_NB;
        int sub = threadIdx.x >> 7;            // 0..7
        int d   = threadIdx.x & 127;
        int s   = vb * 8 + sub;

        __shared__ int s_lo[8], s_hi[8];
        if (s < N_STRUCT) {
            if (d == 0) {
                int lo = 0, hi = N_SAMP;
                while (lo < hi) { int m = (lo + hi) >> 1; if (sid[m] < s) lo = m + 1; else hi = m; }
                s_lo[sub] = lo;
                lo = s_lo[sub]; hi = N_SAMP;
                while (lo < hi) { int m = (lo + hi) >> 1; if (sid[m] < s + 1) lo = m + 1; else hi = m; }
                s_hi[sub] = lo;
            }
        }
        __syncthreads();
        if (s >= N_STRUCT) return;

        int lo = s_lo[sub], hi = s_hi[sub];
        float a0 = 0.f, a1 = 0.f, a2 = 0.f, a3 = 0.f;
        int r = lo;
        for (; r + 3 < hi; r += 4) {
            a0 += __ldcs(values + (long long)(r    ) * DFEAT + d);
            a1 += __ldcs(values + (long long)(r + 1) * DFEAT + d);
            a2 += __ldcs(values + (long long)(r + 2) * DFEAT + d);
            a3 += __ldcs(values + (long long)(r + 3) * DFEAT + d);
        }
        for (; r < hi; ++r)
            a0 += __ldcs(values + (long long)r * DFEAT + d);
        __stcs(out + (long long)s * DFEAT + d, (a0 + a1) + (a2 + a3));
    }
}

// ---------------------------------------------------------------------------
// Kernel 2: gather-reduce — EXACT proven hot path (145us @ 6.1+TB/s).
// One warp per segment; row ids prefetched into lanes + shfl broadcast ->
// all 3*cnt loads address-ready. Restores all scratch invariants.
// ---------------------------------------------------------------------------
__global__ void gather_kernel(const float4* __restrict__ grad4,
                              float*        __restrict__ out_grad) {
    int zi = blockIdx.x * 256 + threadIdx.x;
    if (zi < NSEG) g_count[zi] = 0;
    if (zi < WORK_NB) g_bsum[zi] = 0;
    if (zi == 0) { g_sync1 = 0; g_sync2 = 0; }

    int warp_id = (blockIdx.x * 256 + threadIdx.x) >> 5;
    int lane    = threadIdx.x & 31;

    int lo  = g_start[warp_id];
    int hi  = g_start[warp_id + 1];
    int cnt = hi - lo;

    int rid = (lane < cnt) ? g_rows[lo + lane] : 0;

    float4 a0 = make_float4(0.f, 0.f, 0.f, 0.f);
    float4 a1 = a0, a2 = a0;

    int n32 = cnt < 32 ? cnt : 32;
    #pragma unroll 4
    for (int p = 0; p < n32; ++p) {
        long long row = __shfl_sync(0xffffffffu, rid, p);
        const float4* src = grad4 + row * ROW_F4;
        float4 v0 = __ldcs(src + lane);
        float4 v1 = __ldcs(src + lane + 32);
        float4 v2 = __ldcs(src + lane + 64);
        a0.x += v0.x; a0.y += v0.y; a0.z += v0.z; a0.w += v0.w;
        a1.x += v1.x; a1.y += v1.y; a1.z += v1.z; a1.w += v1.w;
        a2.x += v2.x; a2.y += v2.y; a2.z += v2.z; a2.w += v2.w;
    }
    for (int p = 32; p < cnt; ++p) {         // overflow fallback (never hit)
        long long row = g_rows[lo + p];
        const float4* src = grad4 + row * ROW_F4;
        float4 v0 = __ldcs(src + lane);
        float4 v1 = __ldcs(src + lane + 32);
        float4 v2 = __ldcs(src + lane + 64);
        a0.x += v0.x; a0.y += v0.y; a0.z += v0.z; a0.w += v0.w;
        a1.x += v1.x; a1.y += v1.y; a1.z += v1.z; a1.w += v1.w;
        a2.x += v2.x; a2.y += v2.y; a2.z += v2.z; a2.w += v2.w;
    }

    float4* dst = (float4*)(out_grad + (long long)warp_id * (3 * DFEAT));
    __stcs(dst + lane,      a0);
    __stcs(dst + lane + 32, a1);
    __stcs(dst + lane + 64, a2);
}

// ---------------------------------------------------------------------------
extern "C" void kernel_launch(void* const* d_in, const int* in_sizes, int n_in,
                              void* d_out, int out_size) {
    const float*  values  = (const float*)d_in[0];
    const int*    sid     = (const int*)  d_in[1];
    const float4* grad4   = (const float4*)d_in[2];
    const int*    gstruct = (const int*)  d_in[3];
    const int*    gatom   = (const int*)  d_in[4];

    float* out      = (float*)d_out;
    float* out_grad = out + GRAD_OUT_OFFSET;

    prep_kernel<<<PREP_BLOCKS, 1024>>>(gstruct, gatom, values, sid, out);
    gather_kernel<<<GATHER_BLOCKS, 256>>>(grad4, out_grad);
}

// round 14
// speedup vs baseline: 1.0100x; 1.0079x over previous
#include <cuda_runtime.h>
#include <stdint.h>

#define N_STRUCT   1000
#define ATOMS      100
#define N_SAMP     100000
#define N_GRAD     500000
#define DFEAT      128
#define NSEG       (N_STRUCT * ATOMS)      // 100000
#define ROW_F4     96                      // 3*128/4
#define GRAD_OUT_OFFSET (N_STRUCT * DFEAT)

// prep: 148 worker blocks (1/SM), tile 680 segments each (148*680 >= 100000)
#define WORK_NB    148
#define TILE       680
#define PREP_THREADS (WORK_NB * 1024)          // 151552

#define VALUES_NB  ((N_STRUCT + 7) / 8)        // 125
#define PREP_BLOCKS (WORK_NB + VALUES_NB)      // 273 (all co-resident)

#define GATHER_BLOCKS (NSEG / 8)               // 12500 (8 warps/blk, 1 seg/warp)

// -------- scratch (device globals; zero-initialized at module load) --------
// Invariants at kernel_launch entry (restored by gather every call):
//   g_count == 0, g_bsum == 0, g_sync1 == 0, g_sync2 == 0
__device__ int g_count[NSEG];
__device__ int g_start[NSEG + 1];
__device__ int g_rows[N_GRAD];
__device__ int g_segpos[N_GRAD];   // (seg << 8) | within-segment rank
__device__ int g_bsum[WORK_NB];    // tile-sum + 1 (0 == not ready)
__device__ int g_sync1, g_sync2;   // grid-sync counters (worker blocks only)

// ---------------------------------------------------------------------------
// Kernel 1 (persistent prep) — worker branch byte-identical to R11 (best):
//   bid <  WORK_NB : count -> gridsync -> scan(+lookback) -> gridsync -> scatter
//   bid >= WORK_NB : values segment-sums, now with 8-way MLP
// ---------------------------------------------------------------------------
__global__ __launch_bounds__(1024) void prep_kernel(
        const int*   __restrict__ gstruct,
        const int*   __restrict__ gatom,
        const float* __restrict__ values,
        const int*   __restrict__ sid,
        float*       __restrict__ out) {
    if (blockIdx.x < WORK_NB) {
        int tid = threadIdx.x;
        int b   = blockIdx.x;
        int gth = b * 1024 + tid;

        // --- phase 1: degree count; atomicAdd return value = rank ---
        for (int r = gth; r < N_GRAD; r += PREP_THREADS) {
            int seg = __ldcs(gstruct + r) * ATOMS + __ldcs(gatom + r);
            int pos = atomicAdd(&g_count[seg], 1);
            g_segpos[r] = (seg << 8) | pos;          // pos <= ~25
        }
        __syncthreads();
        if (tid == 0) {
            __threadfence();
            atomicAdd(&g_sync1, 1);
            volatile int* p = &g_sync1;
            while (*p < WORK_NB) { }
        }
        __syncthreads();

        // --- phase 2: tile scan (680 segs/block) + decoupled lookback ---
        __shared__ int sh[1024];
        __shared__ int s_boff;
        int i = b * TILE + tid;                      // tid < TILE valid
        int v = (tid < TILE && i < NSEG) ? g_count[i] : 0;
        sh[tid] = v;
        __syncthreads();
        for (int off = 1; off < 1024; off <<= 1) {
            int t = (tid >= off) ? sh[tid - off] : 0;
            __syncthreads();
            sh[tid] += t;
            __syncthreads();
        }
        if (tid == 1023) {
            volatile int* p = g_bsum;
            p[b] = sh[1023] + 1;                     // tile total (+1 = ready)
        }
        if (tid < 32) {                               // lookback j < b
            int acc = 0;
            volatile int* p = g_bsum;
            for (int j = tid; j < b; j += 32) {
                int w;
                while ((w = p[j]) == 0) { }
                acc += w - 1;
            }
            #pragma unroll
            for (int off = 16; off > 0; off >>= 1)
                acc += __shfl_down_sync(0xffffffffu, acc, off);
            if (tid == 0) s_boff = acc;
        }
        __syncthreads();
        if (tid < TILE && i < NSEG) g_start[i] = sh[tid] - v + s_boff;
        if (i == NSEG - 1) g_start[NSEG] = N_GRAD;

        __syncthreads();
        if (tid == 0) {
            __threadfence();
            atomicAdd(&g_sync2, 1);
            volatile int* p = &g_sync2;
            while (*p < WORK_NB) { }
        }
        __syncthreads();

        // --- phase 3: atomic-free scatter ---
        for (int r = gth; r < N_GRAD; r += PREP_THREADS) {
            int sp  = g_segpos[r];
            int seg = sp >> 8;
            g_rows[g_start[seg] + (sp & 255)] = r;
        }
    } else {
        // --- values segment-sum: 8 structures per block (sorted -> bsearch),
        //     8 independent accumulators -> 8x MLP on the latency chain.
        int vb  = blockIdx.x - WORK_NB;
        int sub = threadIdx.x >> 7;            // 0..7
        int d   = threadIdx.x & 127;
        int s   = vb * 8 + sub;

        __shared__ int s_lo[8], s_hi[8];
        if (s < N_STRUCT) {
            if (d == 0) {
                int lo = 0, hi = N_SAMP;
                while (lo < hi) { int m = (lo + hi) >> 1; if (sid[m] < s) lo = m + 1; else hi = m; }
                s_lo[sub] = lo;
                lo = s_lo[sub]; hi = N_SAMP;
                while (lo < hi) { int m = (lo + hi) >> 1; if (sid[m] < s + 1) lo = m + 1; else hi = m; }
                s_hi[sub] = lo;
            }
        }
        __syncthreads();
        if (s >= N_STRUCT) return;

        int lo = s_lo[sub], hi = s_hi[sub];
        float a0 = 0.f, a1 = 0.f, a2 = 0.f, a3 = 0.f;
        float a4 = 0.f, a5 = 0.f, a6 = 0.f, a7 = 0.f;
        int r = lo;
        for (; r + 7 < hi; r += 8) {
            a0 += __ldcs(values + (long long)(r    ) * DFEAT + d);
            a1 += __ldcs(values + (long long)(r + 1) * DFEAT + d);
            a2 += __ldcs(values + (long long)(r + 2) * DFEAT + d);
            a3 += __ldcs(values + (long long)(r + 3) * DFEAT + d);
            a4 += __ldcs(values + (long long)(r + 4) * DFEAT + d);
            a5 += __ldcs(values + (long long)(r + 5) * DFEAT + d);
            a6 += __ldcs(values + (long long)(r + 6) * DFEAT + d);
            a7 += __ldcs(values + (long long)(r + 7) * DFEAT + d);
        }
        for (; r < hi; ++r)
            a0 += __ldcs(values + (long long)r * DFEAT + d);
        float acc = ((a0 + a1) + (a2 + a3)) + ((a4 + a5) + (a6 + a7));
        __stcs(out + (long long)s * DFEAT + d, acc);
    }
}

// ---------------------------------------------------------------------------
// Kernel 2: gather-reduce — EXACT proven hot path (145us @ 6.1+TB/s).
// One warp per segment; row ids prefetched into lanes + shfl broadcast ->
// all 3*cnt loads address-ready. Restores all scratch invariants.
// ---------------------------------------------------------------------------
__global__ void gather_kernel(const float4* __restrict__ grad4,
                              float*        __restrict__ out_grad) {
    int zi = blockIdx.x * 256 + threadIdx.x;
    if (zi < NSEG) g_count[zi] = 0;
    if (zi < WORK_NB) g_bsum[zi] = 0;
    if (zi == 0) { g_sync1 = 0; g_sync2 = 0; }

    int warp_id = (blockIdx.x * 256 + threadIdx.x) >> 5;
    int lane    = threadIdx.x & 31;

    int lo  = g_start[warp_id];
    int hi  = g_start[warp_id + 1];
    int cnt = hi - lo;

    int rid = (lane < cnt) ? g_rows[lo + lane] : 0;

    float4 a0 = make_float4(0.f, 0.f, 0.f, 0.f);
    float4 a1 = a0, a2 = a0;

    int n32 = cnt < 32 ? cnt : 32;
    #pragma unroll 4
    for (int p = 0; p < n32; ++p) {
        long long row = __shfl_sync(0xffffffffu, rid, p);
        const float4* src = grad4 + row * ROW_F4;
        float4 v0 = __ldcs(src + lane);
        float4 v1 = __ldcs(src + lane + 32);
        float4 v2 = __ldcs(src + lane + 64);
        a0.x += v0.x; a0.y += v0.y; a0.z += v0.z; a0.w += v0.w;
        a1.x += v1.x; a1.y += v1.y; a1.z += v1.z; a1.w += v1.w;
        a2.x += v2.x; a2.y += v2.y; a2.z += v2.z; a2.w += v2.w;
    }
    for (int p = 32; p < cnt; ++p) {         // overflow fallback (never hit)
        long long row = g_rows[lo + p];
        const float4* src = grad4 + row * ROW_F4;
        float4 v0 = __ldcs(src + lane);
        float4 v1 = __ldcs(src + lane + 32);
        float4 v2 = __ldcs(src + lane + 64);
        a0.x += v0.x; a0.y += v0.y; a0.z += v0.z; a0.w += v0.w;
        a1.x += v1.x; a1.y += v1.y; a1.z += v1.z; a1.w += v1.w;
        a2.x += v2.x; a2.y += v2.y; a2.z += v2.z; a2.w += v2.w;
    }

    float4* dst = (float4*)(out_grad + (long long)warp_id * (3 * DFEAT));
    __stcs(dst + lane,      a0);
    __stcs(dst + lane + 32, a1);
    __stcs(dst + lane + 64, a2);
}

// ---------------------------------------------------------------------------
extern "C" void kernel_launch(void* const* d_in, const int* in_sizes, int n_in,
                              void* d_out, int out_size) {
    const float*  values  = (const float*)d_in[0];
    const int*    sid     = (const int*)  d_in[1];
    const float4* grad4   = (const float4*)d_in[2];
    const int*    gstruct = (const int*)  d_in[3];
    const int*    gatom   = (const int*)  d_in[4];

    float* out      = (float*)d_out;
    float* out_grad = out + GRAD_OUT_OFFSET;

    prep_kernel<<<PREP_BLOCKS, 1024>>>(gstruct, gatom, values, sid, out);
    gather_kernel<<<GATHER_BLOCKS, 256>>>(grad4, out_grad);
}

// round 15
// speedup vs baseline: 1.0211x; 1.0110x over previous
#include <cuda_runtime.h>
#include <stdint.h>

#define N_STRUCT   1000
#define ATOMS      100
#define N_SAMP     100000
#define N_GRAD     500000
#define DFEAT      128
#define NSEG       (N_STRUCT * ATOMS)      // 100000
#define ROW_F4     96                      // 3*128/4
#define GRAD_OUT_OFFSET (N_STRUCT * DFEAT)

// prep: 148 worker blocks (1/SM), tile 680 segments each (148*680 >= 100000)
#define WORK_NB    148
#define TILE       680
#define PREP_THREADS (WORK_NB * 1024)          // 151552

#define VALUES_NB  ((N_STRUCT + 7) / 8)        // 125
#define PREP_BLOCKS (WORK_NB + VALUES_NB)      // 273 (all co-resident)

#define GATHER_BLOCKS (NSEG / 8)               // 12500 (8 warps/blk, 1 seg/warp)

// -------- scratch (device globals; zero-initialized at module load) --------
// Invariants at kernel_launch entry (restored by gather every call):
//   g_count == 0, g_bsum == 0, g_sync1 == 0, g_sync2 == 0
__device__ int g_count[NSEG];
__device__ int g_start[NSEG + 1];
__device__ int g_rows[N_GRAD];
__device__ int g_segpos[N_GRAD];   // (seg << 8) | within-segment rank
__device__ int g_bsum[WORK_NB];    // tile-sum + 1 (0 == not ready)
__device__ int g_sync1, g_sync2;   // grid-sync counters (worker blocks only)

// ---------------------------------------------------------------------------
// Warp-cooperative 32-ary lower_bound: first index i with sid[i] >= target.
// 5 dependent-load rounds instead of 17 (serial bsearch). All lanes uniform.
// ---------------------------------------------------------------------------
__device__ __forceinline__ int warp_lower_bound(const int* __restrict__ sid,
                                                int target, int lane) {
    int lo = 0, hi = N_SAMP;                 // answer in [lo, hi]
    while (hi > lo) {
        int m    = hi - lo;
        int step = (m + 31) >> 5;            // ceil(m/32)
        int p    = lo + lane * step;         // lane 0 probes lo
        bool pred = (p >= hi) ? true : (sid[p] >= target);
        unsigned bal = __ballot_sync(0xffffffffu, pred);
        int j = (bal == 0) ? 32 : (__ffs(bal) - 1);   // first true lane
        if (j == 0) { hi = lo; break; }               // answer == lo
        int pj_1 = lo + (j - 1) * step;               // last false probe
        int pj   = lo + j * step;
        lo = pj_1 + 1;
        if (j < 32) { int nh = pj < hi ? pj : hi; hi = nh; }
    }
    return lo;
}

// ---------------------------------------------------------------------------
// Kernel 1 (persistent prep) — worker branch identical to proven R11:
//   bid <  WORK_NB : count -> gridsync -> scan(+lookback) -> gridsync -> scatter
//   bid >= WORK_NB : values segment-sums (warp 32-ary search + 8-way MLP sum)
// ---------------------------------------------------------------------------
__global__ __launch_bounds__(1024) void prep_kernel(
        const int*   __restrict__ gstruct,
        const int*   __restrict__ gatom,
        const float* __restrict__ values,
        const int*   __restrict__ sid,
        float*       __restrict__ out) {
    if (blockIdx.x < WORK_NB) {
        int tid = threadIdx.x;
        int b   = blockIdx.x;
        int gth = b * 1024 + tid;

        // --- phase 1: degree count; atomicAdd return value = rank ---
        for (int r = gth; r < N_GRAD; r += PREP_THREADS) {
            int seg = __ldcs(gstruct + r) * ATOMS + __ldcs(gatom + r);
            int pos = atomicAdd(&g_count[seg], 1);
            g_segpos[r] = (seg << 8) | pos;          // pos <= ~25
        }
        __syncthreads();
        if (tid == 0) {
            __threadfence();
            atomicAdd(&g_sync1, 1);
            volatile int* p = &g_sync1;
            while (*p < WORK_NB) { }
        }
        __syncthreads();

        // --- phase 2: tile scan (680 segs/block) + decoupled lookback ---
        __shared__ int sh[1024];
        __shared__ int s_boff;
        int i = b * TILE + tid;
        int v = (tid < TILE && i < NSEG) ? g_count[i] : 0;
        sh[tid] = v;
        __syncthreads();
        for (int off = 1; off < 1024; off <<= 1) {
            int t = (tid >= off) ? sh[tid - off] : 0;
            __syncthreads();
            sh[tid] += t;
            __syncthreads();
        }
        if (tid == 1023) {
            volatile int* p = g_bsum;
            p[b] = sh[1023] + 1;                     // tile total (+1 = ready)
        }
        if (tid < 32) {                               // lookback j < b
            int acc = 0;
            volatile int* p = g_bsum;
            for (int j = tid; j < b; j += 32) {
                int w;
                while ((w = p[j]) == 0) { }
                acc += w - 1;
            }
            #pragma unroll
            for (int off = 16; off > 0; off >>= 1)
                acc += __shfl_down_sync(0xffffffffu, acc, off);
            if (tid == 0) s_boff = acc;
        }
        __syncthreads();
        if (tid < TILE && i < NSEG) g_start[i] = sh[tid] - v + s_boff;
        if (i == NSEG - 1) g_start[NSEG] = N_GRAD;

        __syncthreads();
        if (tid == 0) {
            __threadfence();
            atomicAdd(&g_sync2, 1);
            volatile int* p = &g_sync2;
            while (*p < WORK_NB) { }
        }
        __syncthreads();

        // --- phase 3: atomic-free scatter ---
        for (int r = gth; r < N_GRAD; r += PREP_THREADS) {
            int sp  = g_segpos[r];
            int seg = sp >> 8;
            g_rows[g_start[seg] + (sp & 255)] = r;
        }
    } else {
        // --- values segment-sum: 8 structures per block; boundaries via
        //     warp-cooperative 32-ary search (warp0->lo, warp1->hi, parallel)
        int vb  = blockIdx.x - WORK_NB;
        int sub = threadIdx.x >> 7;            // 0..7
        int d   = threadIdx.x & 127;
        int s   = vb * 8 + sub;
        int gw   = d >> 5;                     // warp within 128-group: 0..3
        int lane = d & 31;

        __shared__ int s_lo[8], s_hi[8];
        if (s < N_STRUCT && gw < 2) {
            int res = warp_lower_bound(sid, s + gw, lane);
            if (lane == 0) {
                if (gw == 0) s_lo[sub] = res; else s_hi[sub] = res;
            }
        }
        __syncthreads();
        if (s >= N_STRUCT) return;

        int lo = s_lo[sub], hi = s_hi[sub];
        float a0 = 0.f, a1 = 0.f, a2 = 0.f, a3 = 0.f;
        float a4 = 0.f, a5 = 0.f, a6 = 0.f, a7 = 0.f;
        int r = lo;
        for (; r + 7 < hi; r += 8) {
            a0 += __ldcs(values + (long long)(r    ) * DFEAT + d);
            a1 += __ldcs(values + (long long)(r + 1) * DFEAT + d);
            a2 += __ldcs(values + (long long)(r + 2) * DFEAT + d);
            a3 += __ldcs(values + (long long)(r + 3) * DFEAT + d);
            a4 += __ldcs(values + (long long)(r + 4) * DFEAT + d);
            a5 += __ldcs(values + (long long)(r + 5) * DFEAT + d);
            a6 += __ldcs(values + (long long)(r + 6) * DFEAT + d);
            a7 += __ldcs(values + (long long)(r + 7) * DFEAT + d);
        }
        for (; r < hi; ++r)
            a0 += __ldcs(values + (long long)r * DFEAT + d);
        float acc = ((a0 + a1) + (a2 + a3)) + ((a4 + a5) + (a6 + a7));
        __stcs(out + (long long)s * DFEAT + d, acc);
    }
}

// ---------------------------------------------------------------------------
// Kernel 2: gather-reduce — EXACT proven hot path (145us @ 6.1+TB/s).
// One warp per segment; row ids prefetched into lanes + shfl broadcast ->
// all 3*cnt loads address-ready. Restores all scratch invariants.
// ---------------------------------------------------------------------------
__global__ void gather_kernel(const float4* __restrict__ grad4,
                              float*        __restrict__ out_grad) {
    int zi = blockIdx.x * 256 + threadIdx.x;
    if (zi < NSEG) g_count[zi] = 0;
    if (zi < WORK_NB) g_bsum[zi] = 0;
    if (zi == 0) { g_sync1 = 0; g_sync2 = 0; }

    int warp_id = (blockIdx.x * 256 + threadIdx.x) >> 5;
    int lane    = threadIdx.x & 31;

    int lo  = g_start[warp_id];
    int hi  = g_start[warp_id + 1];
    int cnt = hi - lo;

    int rid = (lane < cnt) ? g_rows[lo + lane] : 0;

    float4 a0 = make_float4(0.f, 0.f, 0.f, 0.f);
    float4 a1 = a0, a2 = a0;

    int n32 = cnt < 32 ? cnt : 32;
    #pragma unroll 4
    for (int p = 0; p < n32; ++p) {
        long long row = __shfl_sync(0xffffffffu, rid, p);
        const float4* src = grad4 + row * ROW_F4;
        float4 v0 = __ldcs(src + lane);
        float4 v1 = __ldcs(src + lane + 32);
        float4 v2 = __ldcs(src + lane + 64);
        a0.x += v0.x; a0.y += v0.y; a0.z += v0.z; a0.w += v0.w;
        a1.x += v1.x; a1.y += v1.y; a1.z += v1.z; a1.w += v1.w;
        a2.x += v2.x; a2.y += v2.y; a2.z += v2.z; a2.w += v2.w;
    }
    for (int p = 32; p < cnt; ++p) {         // overflow fallback (never hit)
        long long row = g_rows[lo + p];
        const float4* src = grad4 + row * ROW_F4;
        float4 v0 = __ldcs(src + lane);
        float4 v1 = __ldcs(src + lane + 32);
        float4 v2 = __ldcs(src + lane + 64);
        a0.x += v0.x; a0.y += v0.y; a0.z += v0.z; a0.w += v0.w;
        a1.x += v1.x; a1.y += v1.y; a1.z += v1.z; a1.w += v1.w;
        a2.x += v2.x; a2.y += v2.y; a2.z += v2.z; a2.w += v2.w;
    }

    float4* dst = (float4*)(out_grad + (long long)warp_id * (3 * DFEAT));
    __stcs(dst + lane,      a0);
    __stcs(dst + lane + 32, a1);
    __stcs(dst + lane + 64, a2);
}

// ---------------------------------------------------------------------------
extern "C" void kernel_launch(void* const* d_in, const int* in_sizes, int n_in,
                              void* d_out, int out_size) {
    const float*  values  = (const float*)d_in[0];
    const int*    sid     = (const int*)  d_in[1];
    const float4* grad4   = (const float4*)d_in[2];
    const int*    gstruct = (const int*)  d_in[3];
    const int*    gatom   = (const int*)  d_in[4];

    float* out      = (float*)d_out;
    float* out_grad = out + GRAD_OUT_OFFSET;

    prep_kernel<<<PREP_BLOCKS, 1024>>>(gstruct, gatom, values, sid, out);
    gather_kernel<<<GATHER_BLOCKS, 256>>>(grad4, out_grad);
}